// round 6
// baseline (speedup 1.0000x reference)
#include <cuda_runtime.h>
#include <cuda_bf16.h>
#include <math.h>

// Problem constants (match reference)
#define N_SRC0 100000
#define N_DST0 20000
#define N_DST1 4096
#define FDIM   256           // feature dim, floats
#define FDIM4  (FDIM/4)      // 64 float4s per row
#define E0_MAX 640000
#define E1_MAX 131072

// ---------------- device scratch (no allocations allowed) ----------------
__device__ float4 g_agg0[(size_t)N_DST0 * FDIM4];   // 20000 x 256 f32
__device__ float4 g_x   [(size_t)N_DST0 * FDIM4];   // layer0 output
__device__ float4 g_agg1[(size_t)N_DST1 * FDIM4];   // 4096 x 256 f32

__device__ int   g_deg_out0[N_SRC0];
__device__ int   g_deg_in0 [N_DST0];
__device__ int   g_deg_out1[N_DST0];
__device__ int   g_deg_in1 [N_DST1];

__device__ float g_nsrc0[N_SRC0];
__device__ float g_ndst0[N_DST0];
__device__ float g_nsrc1[N_DST0];
__device__ float g_ndst1[N_DST1];

// CSR (dst-sorted edge lists) + per-edge weights
__device__ int   g_row0[N_DST0 + 1];
__device__ int   g_cur0[N_DST0];
__device__ int   g_eidx0[E0_MAX];
__device__ float g_ew0  [E0_MAX];
__device__ int   g_row1[N_DST1 + 1];
__device__ int   g_cur1[N_DST1];
__device__ int   g_eidx1[E1_MAX];
__device__ float g_ew1  [E1_MAX];

// ---------------- zero small scratch (deg arrays only) ----------------
__global__ void zero_kernel() {
    const int tid = blockIdx.x * blockDim.x + threadIdx.x;
    const int stride = gridDim.x * blockDim.x;
    for (int i = tid; i < N_SRC0; i += stride) g_deg_out0[i] = 0;
    for (int i = tid; i < N_DST0; i += stride) { g_deg_in0[i] = 0; g_deg_out1[i] = 0; }
    for (int i = tid; i < N_DST1; i += stride) g_deg_in1[i] = 0;
}

// ---------------- degree counting ----------------
__global__ void deg_kernel(const int* __restrict__ src0, const int* __restrict__ dst0, int E0,
                           const int* __restrict__ src1, const int* __restrict__ dst1, int E1) {
    const int tid = blockIdx.x * blockDim.x + threadIdx.x;
    const int stride = gridDim.x * blockDim.x;
    for (int e = tid; e < E0; e += stride) {
        atomicAdd(&g_deg_out0[src0[e]], 1);
        atomicAdd(&g_deg_in0 [dst0[e]], 1);
    }
    for (int e = tid; e < E1; e += stride) {
        atomicAdd(&g_deg_out1[src1[e]], 1);
        atomicAdd(&g_deg_in1 [dst1[e]], 1);
    }
}

// ---------------- norms: clip(deg,1)^-0.5 ----------------
__global__ void norm_kernel() {
    const int i = blockIdx.x * blockDim.x + threadIdx.x;
    if (i < N_SRC0) g_nsrc0[i] = rsqrtf(fmaxf((float)g_deg_out0[i], 1.f));
    if (i < N_DST0) {
        g_ndst0[i] = rsqrtf(fmaxf((float)g_deg_in0 [i], 1.f));
        g_nsrc1[i] = rsqrtf(fmaxf((float)g_deg_out1[i], 1.f));
    }
    if (i < N_DST1) g_ndst1[i] = rsqrtf(fmaxf((float)g_deg_in1[i], 1.f));
}

// ---------------- exclusive prefix scan of deg_in -> row offsets (one block) ----------------
// Warp-shuffle scan: values cached in registers, 2 barriers per layer.
__global__ __launch_bounds__(1024) void scan_kernel() {
    __shared__ int warpsum[32];
    const int t = threadIdx.x;
    const int lane = t & 31;
    const int warp = t >> 5;

    // ----- layer 0: PER=20 (1024*20 = 20480 >= 20000) -----
    {
        int vals[20];
        const int base = t * 20;
        int sum = 0;
#pragma unroll
        for (int i = 0; i < 20; i++) {
            const int idx = base + i;
            vals[i] = (idx < N_DST0) ? g_deg_in0[idx] : 0;
            sum += vals[i];
        }
        int incl = sum;
#pragma unroll
        for (int off = 1; off < 32; off <<= 1) {
            const int n = __shfl_up_sync(0xFFFFFFFFu, incl, off);
            if (lane >= off) incl += n;
        }
        if (lane == 31) warpsum[warp] = incl;
        __syncthreads();
        if (warp == 0) {
            int w = warpsum[lane];
#pragma unroll
            for (int off = 1; off < 32; off <<= 1) {
                const int n = __shfl_up_sync(0xFFFFFFFFu, w, off);
                if (lane >= off) w += n;
            }
            warpsum[lane] = w;
        }
        __syncthreads();
        int run = incl - sum + ((warp > 0) ? warpsum[warp - 1] : 0);
#pragma unroll
        for (int i = 0; i < 20; i++) {
            const int idx = base + i;
            if (idx < N_DST0) {
                g_row0[idx] = run;
                g_cur0[idx] = run;
                run += vals[i];
            }
        }
        if (t == 1023) g_row0[N_DST0] = run;
        __syncthreads();
    }

    // ----- layer 1: PER=4 (1024*4 = 4096) -----
    {
        int vals[4];
        const int base = t * 4;
        int sum = 0;
#pragma unroll
        for (int i = 0; i < 4; i++) { vals[i] = g_deg_in1[base + i]; sum += vals[i]; }
        int incl = sum;
#pragma unroll
        for (int off = 1; off < 32; off <<= 1) {
            const int n = __shfl_up_sync(0xFFFFFFFFu, incl, off);
            if (lane >= off) incl += n;
        }
        if (lane == 31) warpsum[warp] = incl;
        __syncthreads();
        if (warp == 0) {
            int w = warpsum[lane];
#pragma unroll
            for (int off = 1; off < 32; off <<= 1) {
                const int n = __shfl_up_sync(0xFFFFFFFFu, w, off);
                if (lane >= off) w += n;
            }
            warpsum[lane] = w;
        }
        __syncthreads();
        int run = incl - sum + ((warp > 0) ? warpsum[warp - 1] : 0);
#pragma unroll
        for (int i = 0; i < 4; i++) {
            g_row1[base + i] = run;
            g_cur1[base + i] = run;
            run += vals[i];
        }
        if (t == 1023) g_row1[N_DST1] = run;
    }
}

// ---------------- fill CSR slots (counting sort by dst) + edge weights ----------------
__global__ void fill_kernel(const int* __restrict__ src0, const int* __restrict__ dst0, int E0,
                            const int* __restrict__ src1, const int* __restrict__ dst1, int E1) {
    const int tid = blockIdx.x * blockDim.x + threadIdx.x;
    const int stride = gridDim.x * blockDim.x;
    for (int e = tid; e < E0; e += stride) {
        const int s = src0[e];
        const int pos = atomicAdd(&g_cur0[dst0[e]], 1);
        g_eidx0[pos] = s;
        g_ew0[pos]   = g_nsrc0[s];
    }
    for (int e = tid; e < E1; e += stride) {
        const int s = src1[e];
        const int pos = atomicAdd(&g_cur1[dst1[e]], 1);
        g_eidx1[pos] = s;
        g_ew1[pos]   = g_nsrc1[s];
    }
}

// ---------------- gather aggregation ----------------
// agg[r] = sum_{e in row r} ew[e] * feat[eidx[e]]
// 64 threads per row (one float4 lane each), 4 rows per 256-thread block, unroll 8.
template <int L>
__global__ __launch_bounds__(256) void agg_gather_kernel(const float4* __restrict__ featExt) {
    const float4* __restrict__ feat = (L == 0) ? featExt : (const float4*)g_x;
    const int*    __restrict__ rowo = (L == 0) ? g_row0  : g_row1;
    const int*    __restrict__ eidx = (L == 0) ? g_eidx0 : g_eidx1;
    const float*  __restrict__ ew   = (L == 0) ? g_ew0   : g_ew1;
    float4* outp                    = (L == 0) ? g_agg0  : g_agg1;
    const int nRows                 = (L == 0) ? N_DST0  : N_DST1;

    const int lane = threadIdx.x & 63;
    const int row  = blockIdx.x * 4 + (threadIdx.x >> 6);
    if (row >= nRows) return;

    const int beg = rowo[row];
    const int end = rowo[row + 1];

    float4 acc = make_float4(0.f, 0.f, 0.f, 0.f);
    int e = beg;
    for (; e + 8 <= end; e += 8) {
        int   s[8];
        float n[8];
        float4 v[8];
#pragma unroll
        for (int q = 0; q < 8; q++) s[q] = eidx[e + q];
#pragma unroll
        for (int q = 0; q < 8; q++) n[q] = ew[e + q];
#pragma unroll
        for (int q = 0; q < 8; q++) v[q] = feat[(size_t)s[q] * FDIM4 + lane];
#pragma unroll
        for (int q = 0; q < 8; q++) {
            acc.x += n[q] * v[q].x;
            acc.y += n[q] * v[q].y;
            acc.z += n[q] * v[q].z;
            acc.w += n[q] * v[q].w;
        }
    }
    for (; e < end; e++) {
        const int s = eidx[e];
        const float n = ew[e];
        const float4 v = feat[(size_t)s * FDIM4 + lane];
        acc.x += n * v.x; acc.y += n * v.y; acc.z += n * v.z; acc.w += n * v.w;
    }
    outp[(size_t)row * FDIM4 + lane] = acc;
}

// ---------------- packed f32x2 helpers ----------------
__device__ __forceinline__ unsigned long long pack2(float lo, float hi) {
    unsigned long long r;
    asm("mov.b64 %0, {%1, %2};" : "=l"(r) : "f"(lo), "f"(hi));
    return r;
}
__device__ __forceinline__ void unpack2(unsigned long long v, float& lo, float& hi) {
    asm("mov.b64 {%0, %1}, %2;" : "=f"(lo), "=f"(hi) : "l"(v));
}
__device__ __forceinline__ unsigned long long fma2(unsigned long long a,
                                                   unsigned long long b,
                                                   unsigned long long c) {
    unsigned long long d;
    asm("fma.rn.f32x2 %0, %1, %2, %3;" : "=l"(d) : "l"(a), "l"(b), "l"(c));
    return d;
}

// ---------------- tiled SGEMM (f32x2 packed) with row-scale + bias (+relu) ----------------
// C[m,n] = act( rowscale[m] * sum_k A[m,k]*B[k,n] + bias[n] )
// A tile stored DUPLICATED in smem: As2[k][2*r] = As2[k][2*r+1] = A[...] so an
// LDS.64 directly yields the (a,a) broadcast operand for fma.rn.f32x2.
template <int L>
__global__ __launch_bounds__(256)
void sgemm_kernel(const float* __restrict__ B, const float* __restrict__ bias,
                  float* __restrict__ Cext) {
    const int M = (L == 0) ? N_DST0 : N_DST1;
    const int N = (L == 0) ? 256 : 128;
    const int K = 256;
    const float* __restrict__ A        = (L == 0) ? (const float*)g_agg0 : (const float*)g_agg1;
    const float* __restrict__ rowscale = (L == 0) ? g_ndst0 : g_ndst1;
    float* __restrict__ C              = (L == 0) ? (float*)g_x : Cext;

    __shared__ float As2[8][256];   // duplicated pairs
    __shared__ float Bs [8][128];

    const int tid  = threadIdx.x;
    const int tcol = tid % 16;
    const int trow = tid / 16;
    const int rowBase = blockIdx.y * 128;
    const int colBase = blockIdx.x * 128;

    const int aRow = tid >> 1;
    const int aK   = (tid & 1) * 4;
    const int bK   = tid >> 5;
    const int bCol = (tid & 31) * 4;

    unsigned long long acc2[8][4];
    const unsigned long long z2 = pack2(0.f, 0.f);
#pragma unroll
    for (int i = 0; i < 8; i++)
#pragma unroll
        for (int j = 0; j < 4; j++) acc2[i][j] = z2;

    for (int k0 = 0; k0 < K; k0 += 8) {
        const int gr = rowBase + aRow;
        float4 a4 = make_float4(0.f, 0.f, 0.f, 0.f);
        if (gr < M) a4 = *(const float4*)&A[(size_t)gr * K + k0 + aK];
        *(float2*)&As2[aK + 0][2 * aRow] = make_float2(a4.x, a4.x);
        *(float2*)&As2[aK + 1][2 * aRow] = make_float2(a4.y, a4.y);
        *(float2*)&As2[aK + 2][2 * aRow] = make_float2(a4.z, a4.z);
        *(float2*)&As2[aK + 3][2 * aRow] = make_float2(a4.w, a4.w);
        *(float4*)&Bs[bK][bCol] = *(const float4*)&B[(size_t)(k0 + bK) * N + colBase + bCol];
        __syncthreads();

#pragma unroll
        for (int k = 0; k < 8; k++) {
            const unsigned long long* a2p =
                (const unsigned long long*)&As2[k][trow * 16];
            const ulonglong2 bl0 = *(const ulonglong2*)&Bs[k][tcol * 8];
            const ulonglong2 bl1 = *(const ulonglong2*)&Bs[k][tcol * 8 + 4];
            unsigned long long rb2[4] = {bl0.x, bl0.y, bl1.x, bl1.y};
#pragma unroll
            for (int i = 0; i < 8; i++) {
                const unsigned long long a2 = a2p[i];
#pragma unroll
                for (int j = 0; j < 4; j++) acc2[i][j] = fma2(a2, rb2[j], acc2[i][j]);
            }
        }
        __syncthreads();
    }

#pragma unroll
    for (int i = 0; i < 8; i++) {
        const int row = rowBase + trow * 8 + i;
        if (row >= M) continue;
        const float rs = rowscale[row];
#pragma unroll
        for (int j = 0; j < 4; j++) {
            float lo, hi;
            unpack2(acc2[i][j], lo, hi);
            const int col = colBase + tcol * 8 + j * 2;
            float v0 = fmaf(lo, rs, bias[col]);
            float v1 = fmaf(hi, rs, bias[col + 1]);
            if (L == 0) { v0 = fmaxf(v0, 0.f); v1 = fmaxf(v1, 0.f); }
            C[(size_t)row * N + col]     = v0;
            C[(size_t)row * N + col + 1] = v1;
        }
    }
}

// ---------------- launch ----------------
extern "C" void kernel_launch(void* const* d_in, const int* in_sizes, int n_in,
                              void* d_out, int out_size) {
    const float* features = (const float*)d_in[0];   // [100000, 256]
    const float* W1       = (const float*)d_in[1];   // [256, 256]
    const float* b1       = (const float*)d_in[2];   // [256]
    const float* W2       = (const float*)d_in[3];   // [256, 128]
    const float* b2       = (const float*)d_in[4];   // [128]
    const int*   src0     = (const int*)d_in[5];
    const int*   dst0     = (const int*)d_in[6];
    const int*   src1     = (const int*)d_in[7];
    const int*   dst1     = (const int*)d_in[8];
    const int E0 = in_sizes[5];
    const int E1 = in_sizes[7];
    float* out = (float*)d_out;                       // [4096, 128]

    // 1) zero small scratch (deg arrays)
    zero_kernel<<<512, 256>>>();

    // 2) degrees
    deg_kernel<<<1024, 256>>>(src0, dst0, E0, src1, dst1, E1);

    // 3) norms
    norm_kernel<<<(N_SRC0 + 255) / 256, 256>>>();

    // 4) CSR build: row offsets + slot fill (with edge weights)
    scan_kernel<<<1, 1024>>>();
    fill_kernel<<<1024, 256>>>(src0, dst0, E0, src1, dst1, E1);

    // 5) layer-0 aggregation (gather, no atomics)
    agg_gather_kernel<0><<<(N_DST0 + 3) / 4, 256>>>((const float4*)features);

    // 6) layer-0 dense: x = relu((agg0 * ndst0) @ W1 + b1)
    {
        dim3 grid(256 / 128, (N_DST0 + 127) / 128);
        sgemm_kernel<0><<<grid, 256>>>(W1, b1, nullptr);
    }

    // 7) layer-1 aggregation (gather)
    agg_gather_kernel<1><<<(N_DST1 + 3) / 4, 256>>>(nullptr);

    // 8) layer-1 dense: out = (agg1 * ndst1) @ W2 + b2
    {
        dim3 grid(128 / 128, (N_DST1 + 127) / 128);
        sgemm_kernel<1><<<grid, 256>>>(W2, b2, out);
    }
}

// round 8
// speedup vs baseline: 1.1493x; 1.1493x over previous
#include <cuda_runtime.h>
#include <cuda_bf16.h>
#include <math.h>

// Problem constants (match reference)
#define N_SRC0 100000
#define N_DST0 20000
#define N_DST1 4096
#define FDIM   256           // feature dim, floats
#define FDIM4  (FDIM/4)      // 64 float4s per row
#define E0_MAX 640000
#define E1_MAX 131072

// scan blocking
#define CHUNK  2048
#define NBLK0  10            // ceil(20000/2048)
#define NBLK1  2             // 4096/2048

// ---------------- device scratch (no allocations allowed) ----------------
__device__ float4 g_agg0[(size_t)N_DST0 * FDIM4];
__device__ float4 g_x   [(size_t)N_DST0 * FDIM4];
__device__ float4 g_agg1[(size_t)N_DST1 * FDIM4];

__device__ int   g_deg_out0[N_SRC0];
__device__ int   g_deg_in0 [N_DST0];
__device__ int   g_deg_out1[N_DST0];
__device__ int   g_deg_in1 [N_DST1];

__device__ float g_nsrc0[N_SRC0];
__device__ float g_ndst0[N_DST0];
__device__ float g_nsrc1[N_DST0];
__device__ float g_ndst1[N_DST1];

// CSR (dst-sorted edge lists) + per-edge weights
__device__ int   g_row0[N_DST0 + 1];
__device__ int   g_cur0[N_DST0];
__device__ int   g_eidx0[E0_MAX];
__device__ float g_ew0  [E0_MAX];
__device__ int   g_row1[N_DST1 + 1];
__device__ int   g_cur1[N_DST1];
__device__ int   g_eidx1[E1_MAX];
__device__ float g_ew1  [E1_MAX];

// scan partials
__device__ int g_bsum0[NBLK0];
__device__ int g_boff0[NBLK0];
__device__ int g_bsum1[NBLK1];
__device__ int g_boff1[NBLK1];

// ---------------- zero small scratch (deg arrays only) ----------------
__global__ void zero_kernel() {
    const int tid = blockIdx.x * blockDim.x + threadIdx.x;
    const int stride = gridDim.x * blockDim.x;
    for (int i = tid; i < N_SRC0; i += stride) g_deg_out0[i] = 0;
    for (int i = tid; i < N_DST0; i += stride) { g_deg_in0[i] = 0; g_deg_out1[i] = 0; }
    for (int i = tid; i < N_DST1; i += stride) g_deg_in1[i] = 0;
}

// ---------------- degree counting ----------------
__global__ void deg_kernel(const int* __restrict__ src0, const int* __restrict__ dst0, int E0,
                           const int* __restrict__ src1, const int* __restrict__ dst1, int E1) {
    const int tid = blockIdx.x * blockDim.x + threadIdx.x;
    const int stride = gridDim.x * blockDim.x;
    for (int e = tid; e < E0; e += stride) {
        atomicAdd(&g_deg_out0[src0[e]], 1);
        atomicAdd(&g_deg_in0 [dst0[e]], 1);
    }
    for (int e = tid; e < E1; e += stride) {
        atomicAdd(&g_deg_out1[src1[e]], 1);
        atomicAdd(&g_deg_in1 [dst1[e]], 1);
    }
}

// ---------------- norms: clip(deg,1)^-0.5 ----------------
__global__ void norm_kernel() {
    const int i = blockIdx.x * blockDim.x + threadIdx.x;
    if (i < N_SRC0) g_nsrc0[i] = rsqrtf(fmaxf((float)g_deg_out0[i], 1.f));
    if (i < N_DST0) {
        g_ndst0[i] = rsqrtf(fmaxf((float)g_deg_in0 [i], 1.f));
        g_nsrc1[i] = rsqrtf(fmaxf((float)g_deg_out1[i], 1.f));
    }
    if (i < N_DST1) g_ndst1[i] = rsqrtf(fmaxf((float)g_deg_in1[i], 1.f));
}

// ---------------- scan A: per-block sums (coalesced) ----------------
__global__ __launch_bounds__(256) void scanA_kernel() {
    const int b = blockIdx.x;
    const int t = threadIdx.x;
    const int lane = t & 31, warp = t >> 5;
    const int* __restrict__ deg;
    int n, gbase;
    int* bsum;
    if (b < NBLK0) { deg = g_deg_in0; n = N_DST0; gbase = b * CHUNK; bsum = &g_bsum0[b]; }
    else           { deg = g_deg_in1; n = N_DST1; gbase = (b - NBLK0) * CHUNK; bsum = &g_bsum1[b - NBLK0]; }

    int sum = 0;
#pragma unroll
    for (int i = 0; i < 8; i++) {
        const int idx = gbase + i * 256 + t;
        if (idx < n) sum += deg[idx];
    }
    __shared__ int ws[8];
#pragma unroll
    for (int off = 16; off >= 1; off >>= 1) sum += __shfl_down_sync(0xFFFFFFFFu, sum, off);
    if (lane == 0) ws[warp] = sum;
    __syncthreads();
    if (t == 0) {
        int s = 0;
#pragma unroll
        for (int i = 0; i < 8; i++) s += ws[i];
        *bsum = s;
    }
}

// ---------------- scan B: scan the block sums (trivial) ----------------
__global__ void scanB_kernel(int E0, int E1) {
    if (threadIdx.x == 0) {
        int run = 0;
#pragma unroll
        for (int i = 0; i < NBLK0; i++) { g_boff0[i] = run; run += g_bsum0[i]; }
        g_row0[N_DST0] = E0;
        run = 0;
#pragma unroll
        for (int i = 0; i < NBLK1; i++) { g_boff1[i] = run; run += g_bsum1[i]; }
        g_row1[N_DST1] = E1;
    }
}

// ---------------- scan C: per-block exclusive scan via smem staging ----------------
__global__ __launch_bounds__(256) void scanC_kernel() {
    __shared__ int sh[CHUNK];
    __shared__ int wsum[8];
    const int b = blockIdx.x;
    const int t = threadIdx.x;
    const int lane = t & 31, warp = t >> 5;
    const int* __restrict__ deg;
    int n, gbase, base;
    int *row, *cur;
    if (b < NBLK0) {
        deg = g_deg_in0; n = N_DST0; gbase = b * CHUNK;
        base = g_boff0[b]; row = g_row0; cur = g_cur0;
    } else {
        deg = g_deg_in1; n = N_DST1; gbase = (b - NBLK0) * CHUNK;
        base = g_boff1[b - NBLK0]; row = g_row1; cur = g_cur1;
    }

    // coalesced load into smem
#pragma unroll
    for (int i = 0; i < 8; i++) {
        const int idx = gbase + i * 256 + t;
        sh[i * 256 + t] = (idx < n) ? deg[idx] : 0;
    }
    __syncthreads();

    // per-thread blocked chunk from smem
    int vals[8], sum = 0;
#pragma unroll
    for (int i = 0; i < 8; i++) { vals[i] = sh[t * 8 + i]; sum += vals[i]; }

    int incl = sum;
#pragma unroll
    for (int off = 1; off < 32; off <<= 1) {
        const int v = __shfl_up_sync(0xFFFFFFFFu, incl, off);
        if (lane >= off) incl += v;
    }
    if (lane == 31) wsum[warp] = incl;
    __syncthreads();
    if (warp == 0) {
        int w = (lane < 8) ? wsum[lane] : 0;
#pragma unroll
        for (int off = 1; off < 8; off <<= 1) {
            const int v = __shfl_up_sync(0xFFFFFFFFu, w, off);
            if (lane >= off) w += v;
        }
        if (lane < 8) wsum[lane] = w;
    }
    __syncthreads();

    int run = base + incl - sum + ((warp > 0) ? wsum[warp - 1] : 0);
#pragma unroll
    for (int i = 0; i < 8; i++) { sh[t * 8 + i] = run; run += vals[i]; }
    __syncthreads();

    // coalesced store
#pragma unroll
    for (int i = 0; i < 8; i++) {
        const int idx = gbase + i * 256 + t;
        if (idx < n) {
            const int v = sh[i * 256 + t];
            row[idx] = v;
            cur[idx] = v;
        }
    }
}

// ---------------- fill CSR slots (counting sort by dst) + edge weights ----------------
__global__ void fill_kernel(const int* __restrict__ src0, const int* __restrict__ dst0, int E0,
                            const int* __restrict__ src1, const int* __restrict__ dst1, int E1) {
    const int tid = blockIdx.x * blockDim.x + threadIdx.x;
    const int stride = gridDim.x * blockDim.x;
    for (int e = tid; e < E0; e += stride) {
        const int s = src0[e];
        const int pos = atomicAdd(&g_cur0[dst0[e]], 1);
        g_eidx0[pos] = s;
        g_ew0[pos]   = g_nsrc0[s];
    }
    for (int e = tid; e < E1; e += stride) {
        const int s = src1[e];
        const int pos = atomicAdd(&g_cur1[dst1[e]], 1);
        g_eidx1[pos] = s;
        g_ew1[pos]   = g_nsrc1[s];
    }
}

// ---------------- gather aggregation (round-4 form, unroll 4, ew stream) ----------------
template <int L>
__global__ __launch_bounds__(256) void agg_gather_kernel(const float4* __restrict__ featExt) {
    const float4* __restrict__ feat = (L == 0) ? featExt : (const float4*)g_x;
    const int*    __restrict__ rowo = (L == 0) ? g_row0  : g_row1;
    const int*    __restrict__ eidx = (L == 0) ? g_eidx0 : g_eidx1;
    const float*  __restrict__ ew   = (L == 0) ? g_ew0   : g_ew1;
    float4* outp                    = (L == 0) ? g_agg0  : g_agg1;
    const int nRows                 = (L == 0) ? N_DST0  : N_DST1;

    const int lane = threadIdx.x & 63;
    const int row  = blockIdx.x * 4 + (threadIdx.x >> 6);
    if (row >= nRows) return;

    const int beg = rowo[row];
    const int end = rowo[row + 1];

    float4 acc = make_float4(0.f, 0.f, 0.f, 0.f);
    int e = beg;
    for (; e + 4 <= end; e += 4) {
        const int s0 = eidx[e + 0];
        const int s1 = eidx[e + 1];
        const int s2 = eidx[e + 2];
        const int s3 = eidx[e + 3];
        const float n0 = ew[e + 0];
        const float n1 = ew[e + 1];
        const float n2 = ew[e + 2];
        const float n3 = ew[e + 3];
        const float4 v0 = feat[(size_t)s0 * FDIM4 + lane];
        const float4 v1 = feat[(size_t)s1 * FDIM4 + lane];
        const float4 v2 = feat[(size_t)s2 * FDIM4 + lane];
        const float4 v3 = feat[(size_t)s3 * FDIM4 + lane];
        acc.x += n0 * v0.x; acc.y += n0 * v0.y; acc.z += n0 * v0.z; acc.w += n0 * v0.w;
        acc.x += n1 * v1.x; acc.y += n1 * v1.y; acc.z += n1 * v1.z; acc.w += n1 * v1.w;
        acc.x += n2 * v2.x; acc.y += n2 * v2.y; acc.z += n2 * v2.z; acc.w += n2 * v2.w;
        acc.x += n3 * v3.x; acc.y += n3 * v3.y; acc.z += n3 * v3.z; acc.w += n3 * v3.w;
    }
    for (; e < end; e++) {
        const int s = eidx[e];
        const float n = ew[e];
        const float4 v = feat[(size_t)s * FDIM4 + lane];
        acc.x += n * v.x; acc.y += n * v.y; acc.z += n * v.z; acc.w += n * v.w;
    }
    outp[(size_t)row * FDIM4 + lane] = acc;
}

// ---------------- packed f32x2 helpers ----------------
__device__ __forceinline__ unsigned long long pack2(float lo, float hi) {
    unsigned long long r;
    asm("mov.b64 %0, {%1, %2};" : "=l"(r) : "f"(lo), "f"(hi));
    return r;
}
__device__ __forceinline__ void unpack2(unsigned long long v, float& lo, float& hi) {
    asm("mov.b64 {%0, %1}, %2;" : "=f"(lo), "=f"(hi) : "l"(v));
}
__device__ __forceinline__ unsigned long long fma2(unsigned long long a,
                                                   unsigned long long b,
                                                   unsigned long long c) {
    unsigned long long d;
    asm("fma.rn.f32x2 %0, %1, %2, %3;" : "=l"(d) : "l"(a), "l"(b), "l"(c));
    return d;
}

// ---------------- tiled SGEMM (exact round-4 form) ----------------
template <int L>
__global__ __launch_bounds__(256)
void sgemm_kernel(const float* __restrict__ B, const float* __restrict__ bias,
                  float* __restrict__ Cext) {
    const int M = (L == 0) ? N_DST0 : N_DST1;
    const int N = (L == 0) ? 256 : 128;
    const int K = 256;
    const float* __restrict__ A        = (L == 0) ? (const float*)g_agg0 : (const float*)g_agg1;
    const float* __restrict__ rowscale = (L == 0) ? g_ndst0 : g_ndst1;
    float* __restrict__ C              = (L == 0) ? (float*)g_x : Cext;

    __shared__ float As[8][128];
    __shared__ float Bs[8][128];

    const int tid  = threadIdx.x;
    const int tcol = tid % 16;
    const int trow = tid / 16;
    const int rowBase = blockIdx.y * 128;
    const int colBase = blockIdx.x * 128;

    const int aRow = tid >> 1;
    const int aK   = (tid & 1) * 4;
    const int bK   = tid >> 5;
    const int bCol = (tid & 31) * 4;

    unsigned long long acc2[8][4];
    const unsigned long long z2 = pack2(0.f, 0.f);
#pragma unroll
    for (int i = 0; i < 8; i++)
#pragma unroll
        for (int j = 0; j < 4; j++) acc2[i][j] = z2;

    for (int k0 = 0; k0 < K; k0 += 8) {
        const int gr = rowBase + aRow;
        float4 a4 = make_float4(0.f, 0.f, 0.f, 0.f);
        if (gr < M) a4 = *(const float4*)&A[(size_t)gr * K + k0 + aK];
        As[aK + 0][aRow] = a4.x;
        As[aK + 1][aRow] = a4.y;
        As[aK + 2][aRow] = a4.z;
        As[aK + 3][aRow] = a4.w;
        *(float4*)&Bs[bK][bCol] = *(const float4*)&B[(size_t)(k0 + bK) * N + colBase + bCol];
        __syncthreads();

#pragma unroll
        for (int k = 0; k < 8; k++) {
            const float4 a0 = *(const float4*)&As[k][trow * 8];
            const float4 a1 = *(const float4*)&As[k][trow * 8 + 4];
            const float4 b0 = *(const float4*)&Bs[k][tcol * 8];
            const float4 b1 = *(const float4*)&Bs[k][tcol * 8 + 4];
            unsigned long long rb2[4];
            rb2[0] = pack2(b0.x, b0.y);
            rb2[1] = pack2(b0.z, b0.w);
            rb2[2] = pack2(b1.x, b1.y);
            rb2[3] = pack2(b1.z, b1.w);
            const float ra[8] = {a0.x, a0.y, a0.z, a0.w, a1.x, a1.y, a1.z, a1.w};
#pragma unroll
            for (int i = 0; i < 8; i++) {
                const unsigned long long a2 = pack2(ra[i], ra[i]);
#pragma unroll
                for (int j = 0; j < 4; j++) acc2[i][j] = fma2(a2, rb2[j], acc2[i][j]);
            }
        }
        __syncthreads();
    }

#pragma unroll
    for (int i = 0; i < 8; i++) {
        const int row = rowBase + trow * 8 + i;
        if (row >= M) continue;
        const float rs = rowscale[row];
#pragma unroll
        for (int j = 0; j < 4; j++) {
            float lo, hi;
            unpack2(acc2[i][j], lo, hi);
            const int col = colBase + tcol * 8 + j * 2;
            float v0 = fmaf(lo, rs, bias[col]);
            float v1 = fmaf(hi, rs, bias[col + 1]);
            if (L == 0) { v0 = fmaxf(v0, 0.f); v1 = fmaxf(v1, 0.f); }
            C[(size_t)row * N + col]     = v0;
            C[(size_t)row * N + col + 1] = v1;
        }
    }
}

// ---------------- launch ----------------
extern "C" void kernel_launch(void* const* d_in, const int* in_sizes, int n_in,
                              void* d_out, int out_size) {
    const float* features = (const float*)d_in[0];
    const float* W1       = (const float*)d_in[1];
    const float* b1       = (const float*)d_in[2];
    const float* W2       = (const float*)d_in[3];
    const float* b2       = (const float*)d_in[4];
    const int*   src0     = (const int*)d_in[5];
    const int*   dst0     = (const int*)d_in[6];
    const int*   src1     = (const int*)d_in[7];
    const int*   dst1     = (const int*)d_in[8];
    const int E0 = in_sizes[5];
    const int E1 = in_sizes[7];
    float* out = (float*)d_out;

    // 1) zero small scratch
    zero_kernel<<<512, 256>>>();

    // 2) degrees
    deg_kernel<<<1024, 256>>>(src0, dst0, E0, src1, dst1, E1);

    // 3) norms
    norm_kernel<<<(N_SRC0 + 255) / 256, 256>>>();

    // 4) CSR build: multi-block coalesced scan + slot fill
    scanA_kernel<<<NBLK0 + NBLK1, 256>>>();
    scanB_kernel<<<1, 32>>>(E0, E1);
    scanC_kernel<<<NBLK0 + NBLK1, 256>>>();
    fill_kernel<<<1024, 256>>>(src0, dst0, E0, src1, dst1, E1);

    // 5) layer-0 aggregation (gather, no atomics)
    agg_gather_kernel<0><<<(N_DST0 + 3) / 4, 256>>>((const float4*)features);

    // 6) layer-0 dense: x = relu((agg0 * ndst0) @ W1 + b1)
    {
        dim3 grid(256 / 128, (N_DST0 + 127) / 128);
        sgemm_kernel<0><<<grid, 256>>>(W1, b1, nullptr);
    }

    // 7) layer-1 aggregation (gather)
    agg_gather_kernel<1><<<(N_DST1 + 3) / 4, 256>>>(nullptr);

    // 8) layer-1 dense: out = (agg1 * ndst1) @ W2 + b2
    {
        dim3 grid(128 / 128, (N_DST1 + 127) / 128);
        sgemm_kernel<1><<<grid, 256>>>(W2, b2, out);
    }
}

// round 9
// speedup vs baseline: 1.5786x; 1.3736x over previous
#include <cuda_runtime.h>
#include <cuda_bf16.h>
#include <math.h>

// Problem constants (match reference)
#define N_SRC0 100000
#define N_DST0 20000
#define N_DST1 4096
#define FDIM   256
#define FDIM4  (FDIM/4)
#define E0_MAX 640000
#define E1_MAX 131072

// scan blocking
#define CHUNK  2048
#define NBLK0  10
#define NBLK1  2

// ---------------- device scratch ----------------
__device__ float4 g_agg0[(size_t)N_DST0 * FDIM4];
__device__ float4 g_x   [(size_t)N_DST0 * FDIM4];
__device__ float4 g_agg1[(size_t)N_DST1 * FDIM4];

__device__ int   g_deg_out0[N_SRC0];
__device__ int   g_deg_in0 [N_DST0];
__device__ int   g_deg_out1[N_DST0];
__device__ int   g_deg_in1 [N_DST1];

__device__ float g_nsrc0[N_SRC0];
__device__ float g_ndst0[N_DST0];
__device__ float g_nsrc1[N_DST0];
__device__ float g_ndst1[N_DST1];

__device__ int   g_row0[N_DST0 + 1];
__device__ int   g_cur0[N_DST0];
__device__ int   g_eidx0[E0_MAX];
__device__ float g_ew0  [E0_MAX];
__device__ int   g_row1[N_DST1 + 1];
__device__ int   g_cur1[N_DST1];
__device__ int   g_eidx1[E1_MAX];
__device__ float g_ew1  [E1_MAX];

__device__ int g_bsum0[NBLK0];
__device__ int g_boff0[NBLK0];
__device__ int g_bsum1[NBLK1];
__device__ int g_boff1[NBLK1];

// ---------------- zero small scratch ----------------
__global__ void zero_kernel() {
    const int tid = blockIdx.x * blockDim.x + threadIdx.x;
    const int stride = gridDim.x * blockDim.x;
    for (int i = tid; i < N_SRC0; i += stride) g_deg_out0[i] = 0;
    for (int i = tid; i < N_DST0; i += stride) { g_deg_in0[i] = 0; g_deg_out1[i] = 0; }
    for (int i = tid; i < N_DST1; i += stride) g_deg_in1[i] = 0;
}

// ---------------- degree counting ----------------
__global__ void deg_kernel(const int* __restrict__ src0, const int* __restrict__ dst0, int E0,
                           const int* __restrict__ src1, const int* __restrict__ dst1, int E1) {
    const int tid = blockIdx.x * blockDim.x + threadIdx.x;
    const int stride = gridDim.x * blockDim.x;
    for (int e = tid; e < E0; e += stride) {
        atomicAdd(&g_deg_out0[src0[e]], 1);
        atomicAdd(&g_deg_in0 [dst0[e]], 1);
    }
    for (int e = tid; e < E1; e += stride) {
        atomicAdd(&g_deg_out1[src1[e]], 1);
        atomicAdd(&g_deg_in1 [dst1[e]], 1);
    }
}

// ---------------- norms ----------------
__global__ void norm_kernel() {
    const int i = blockIdx.x * blockDim.x + threadIdx.x;
    if (i < N_SRC0) g_nsrc0[i] = rsqrtf(fmaxf((float)g_deg_out0[i], 1.f));
    if (i < N_DST0) {
        g_ndst0[i] = rsqrtf(fmaxf((float)g_deg_in0 [i], 1.f));
        g_nsrc1[i] = rsqrtf(fmaxf((float)g_deg_out1[i], 1.f));
    }
    if (i < N_DST1) g_ndst1[i] = rsqrtf(fmaxf((float)g_deg_in1[i], 1.f));
}

// ---------------- scan A: per-block sums ----------------
__global__ __launch_bounds__(256) void scanA_kernel() {
    const int b = blockIdx.x;
    const int t = threadIdx.x;
    const int lane = t & 31, warp = t >> 5;
    const int* __restrict__ deg;
    int n, gbase;
    int* bsum;
    if (b < NBLK0) { deg = g_deg_in0; n = N_DST0; gbase = b * CHUNK; bsum = &g_bsum0[b]; }
    else           { deg = g_deg_in1; n = N_DST1; gbase = (b - NBLK0) * CHUNK; bsum = &g_bsum1[b - NBLK0]; }

    int sum = 0;
#pragma unroll
    for (int i = 0; i < 8; i++) {
        const int idx = gbase + i * 256 + t;
        if (idx < n) sum += deg[idx];
    }
    __shared__ int ws[8];
#pragma unroll
    for (int off = 16; off >= 1; off >>= 1) sum += __shfl_down_sync(0xFFFFFFFFu, sum, off);
    if (lane == 0) ws[warp] = sum;
    __syncthreads();
    if (t == 0) {
        int s = 0;
#pragma unroll
        for (int i = 0; i < 8; i++) s += ws[i];
        *bsum = s;
    }
}

// ---------------- scan B ----------------
__global__ void scanB_kernel(int E0, int E1) {
    if (threadIdx.x == 0) {
        int run = 0;
#pragma unroll
        for (int i = 0; i < NBLK0; i++) { g_boff0[i] = run; run += g_bsum0[i]; }
        g_row0[N_DST0] = E0;
        run = 0;
#pragma unroll
        for (int i = 0; i < NBLK1; i++) { g_boff1[i] = run; run += g_bsum1[i]; }
        g_row1[N_DST1] = E1;
    }
}

// ---------------- scan C ----------------
__global__ __launch_bounds__(256) void scanC_kernel() {
    __shared__ int sh[CHUNK];
    __shared__ int wsum[8];
    const int b = blockIdx.x;
    const int t = threadIdx.x;
    const int lane = t & 31, warp = t >> 5;
    const int* __restrict__ deg;
    int n, gbase, base;
    int *row, *cur;
    if (b < NBLK0) {
        deg = g_deg_in0; n = N_DST0; gbase = b * CHUNK;
        base = g_boff0[b]; row = g_row0; cur = g_cur0;
    } else {
        deg = g_deg_in1; n = N_DST1; gbase = (b - NBLK0) * CHUNK;
        base = g_boff1[b - NBLK0]; row = g_row1; cur = g_cur1;
    }

#pragma unroll
    for (int i = 0; i < 8; i++) {
        const int idx = gbase + i * 256 + t;
        sh[i * 256 + t] = (idx < n) ? deg[idx] : 0;
    }
    __syncthreads();

    int vals[8], sum = 0;
#pragma unroll
    for (int i = 0; i < 8; i++) { vals[i] = sh[t * 8 + i]; sum += vals[i]; }

    int incl = sum;
#pragma unroll
    for (int off = 1; off < 32; off <<= 1) {
        const int v = __shfl_up_sync(0xFFFFFFFFu, incl, off);
        if (lane >= off) incl += v;
    }
    if (lane == 31) wsum[warp] = incl;
    __syncthreads();
    if (warp == 0) {
        int w = (lane < 8) ? wsum[lane] : 0;
#pragma unroll
        for (int off = 1; off < 8; off <<= 1) {
            const int v = __shfl_up_sync(0xFFFFFFFFu, w, off);
            if (lane >= off) w += v;
        }
        if (lane < 8) wsum[lane] = w;
    }
    __syncthreads();

    int run = base + incl - sum + ((warp > 0) ? wsum[warp - 1] : 0);
#pragma unroll
    for (int i = 0; i < 8; i++) { sh[t * 8 + i] = run; run += vals[i]; }
    __syncthreads();

#pragma unroll
    for (int i = 0; i < 8; i++) {
        const int idx = gbase + i * 256 + t;
        if (idx < n) {
            const int v = sh[i * 256 + t];
            row[idx] = v;
            cur[idx] = v;
        }
    }
}

// ---------------- fill CSR slots + edge weights ----------------
__global__ void fill_kernel(const int* __restrict__ src0, const int* __restrict__ dst0, int E0,
                            const int* __restrict__ src1, const int* __restrict__ dst1, int E1) {
    const int tid = blockIdx.x * blockDim.x + threadIdx.x;
    const int stride = gridDim.x * blockDim.x;
    for (int e = tid; e < E0; e += stride) {
        const int s = src0[e];
        const int pos = atomicAdd(&g_cur0[dst0[e]], 1);
        g_eidx0[pos] = s;
        g_ew0[pos]   = g_nsrc0[s];
    }
    for (int e = tid; e < E1; e += stride) {
        const int s = src1[e];
        const int pos = atomicAdd(&g_cur1[dst1[e]], 1);
        g_eidx1[pos] = s;
        g_ew1[pos]   = g_nsrc1[s];
    }
}

// ---------------- gather aggregation (unchanged, known-good) ----------------
template <int L>
__global__ __launch_bounds__(256) void agg_gather_kernel(const float4* __restrict__ featExt) {
    const float4* __restrict__ feat = (L == 0) ? featExt : (const float4*)g_x;
    const int*    __restrict__ rowo = (L == 0) ? g_row0  : g_row1;
    const int*    __restrict__ eidx = (L == 0) ? g_eidx0 : g_eidx1;
    const float*  __restrict__ ew   = (L == 0) ? g_ew0   : g_ew1;
    float4* outp                    = (L == 0) ? g_agg0  : g_agg1;
    const int nRows                 = (L == 0) ? N_DST0  : N_DST1;

    const int lane = threadIdx.x & 63;
    const int row  = blockIdx.x * 4 + (threadIdx.x >> 6);
    if (row >= nRows) return;

    const int beg = rowo[row];
    const int end = rowo[row + 1];

    float4 acc = make_float4(0.f, 0.f, 0.f, 0.f);
    int e = beg;
    for (; e + 4 <= end; e += 4) {
        const int s0 = eidx[e + 0];
        const int s1 = eidx[e + 1];
        const int s2 = eidx[e + 2];
        const int s3 = eidx[e + 3];
        const float n0 = ew[e + 0];
        const float n1 = ew[e + 1];
        const float n2 = ew[e + 2];
        const float n3 = ew[e + 3];
        const float4 v0 = feat[(size_t)s0 * FDIM4 + lane];
        const float4 v1 = feat[(size_t)s1 * FDIM4 + lane];
        const float4 v2 = feat[(size_t)s2 * FDIM4 + lane];
        const float4 v3 = feat[(size_t)s3 * FDIM4 + lane];
        acc.x += n0 * v0.x; acc.y += n0 * v0.y; acc.z += n0 * v0.z; acc.w += n0 * v0.w;
        acc.x += n1 * v1.x; acc.y += n1 * v1.y; acc.z += n1 * v1.z; acc.w += n1 * v1.w;
        acc.x += n2 * v2.x; acc.y += n2 * v2.y; acc.z += n2 * v2.z; acc.w += n2 * v2.w;
        acc.x += n3 * v3.x; acc.y += n3 * v3.y; acc.z += n3 * v3.z; acc.w += n3 * v3.w;
    }
    for (; e < end; e++) {
        const int s = eidx[e];
        const float n = ew[e];
        const float4 v = feat[(size_t)s * FDIM4 + lane];
        acc.x += n * v.x; acc.y += n * v.y; acc.z += n * v.z; acc.w += n * v.w;
    }
    outp[(size_t)row * FDIM4 + lane] = acc;
}

// ---------------- TF32 helpers ----------------
__device__ __forceinline__ unsigned f2tf32(float f) {
    unsigned r;
    asm("cvt.rna.tf32.f32 %0, %1;" : "=r"(r) : "f"(f));
    return r;
}
__device__ __forceinline__ void mma_tf32(float* d, const unsigned* a, const unsigned* b) {
    asm("mma.sync.aligned.m16n8k8.row.col.f32.tf32.tf32.f32 "
        "{%0,%1,%2,%3},{%4,%5,%6,%7},{%8,%9},{%0,%1,%2,%3};"
        : "+f"(d[0]), "+f"(d[1]), "+f"(d[2]), "+f"(d[3])
        : "r"(a[0]), "r"(a[1]), "r"(a[2]), "r"(a[3]), "r"(b[0]), "r"(b[1]));
}

// ---------------- TF32 tensor-core GEMM with row-scale + bias (+relu) ----------------
// C[m,n] = act( rowscale[m] * sum_k A[m,k]*B[k,n] + bias[n] )
// Block 128x128, 8 warps (4x2), warp tile 32x64 (2 m-tiles x 8 n-tiles of m16n8k8).
#define A_PAD 12
#define B_PAD 136
template <int L>
__global__ __launch_bounds__(256)
void mma_gemm_kernel(const float* __restrict__ B, const float* __restrict__ bias,
                     float* __restrict__ Cext) {
    const int M = (L == 0) ? N_DST0 : N_DST1;
    const int N = (L == 0) ? 256 : 128;
    const int K = 256;
    const float* __restrict__ A        = (L == 0) ? (const float*)g_agg0 : (const float*)g_agg1;
    const float* __restrict__ rowscale = (L == 0) ? g_ndst0 : g_ndst1;
    float* __restrict__ C              = (L == 0) ? (float*)g_x : Cext;

    __shared__ unsigned As[128 * A_PAD];   // [row][k], stride 12
    __shared__ unsigned Bs[8 * B_PAD];     // [k][n],  stride 136

    const int tid  = threadIdx.x;
    const int wid  = tid >> 5;
    const int lane = tid & 31;
    const int warp_m = wid >> 1;          // 0..3 (32 rows each)
    const int warp_n = wid & 1;           // 0..1 (64 cols each)
    const int g = lane >> 2;              // groupID 0..7
    const int t4 = lane & 3;              // threadID_in_group 0..3

    const int rowBase = blockIdx.y * 128;
    const int colBase = blockIdx.x * 128;

    // tile-load mappings
    const int aRow = tid >> 1;            // 0..127
    const int aH   = (tid & 1) * 4;       // 0 or 4
    const int bK   = tid >> 5;            // 0..7
    const int bCol = (tid & 31) * 4;      // 0..124

    float acc[2][8][4];
#pragma unroll
    for (int mi = 0; mi < 2; mi++)
#pragma unroll
        for (int nt = 0; nt < 8; nt++)
#pragma unroll
            for (int q = 0; q < 4; q++) acc[mi][nt][q] = 0.f;

    for (int k0 = 0; k0 < K; k0 += 8) {
        // A tile: 128 rows x 8 k
        const int gr = rowBase + aRow;
        float4 a4 = make_float4(0.f, 0.f, 0.f, 0.f);
        if (gr < M) a4 = *(const float4*)&A[(size_t)gr * K + k0 + aH];
        unsigned* ap = &As[aRow * A_PAD + aH];
        ap[0] = f2tf32(a4.x); ap[1] = f2tf32(a4.y);
        ap[2] = f2tf32(a4.z); ap[3] = f2tf32(a4.w);
        // B tile: 8 k x 128 n
        const float4 b4 = *(const float4*)&B[(size_t)(k0 + bK) * N + colBase + bCol];
        unsigned* bp = &Bs[bK * B_PAD + bCol];
        bp[0] = f2tf32(b4.x); bp[1] = f2tf32(b4.y);
        bp[2] = f2tf32(b4.z); bp[3] = f2tf32(b4.w);
        __syncthreads();

        // B fragments (independent of mi)
        unsigned bf[8][2];
#pragma unroll
        for (int nt = 0; nt < 8; nt++) {
            const int n = warp_n * 64 + nt * 8 + g;
            bf[nt][0] = Bs[t4 * B_PAD + n];
            bf[nt][1] = Bs[(t4 + 4) * B_PAD + n];
        }
        // A fragments
        unsigned af[2][4];
#pragma unroll
        for (int mi = 0; mi < 2; mi++) {
            const int r0 = warp_m * 32 + mi * 16;
            af[mi][0] = As[(r0 + g) * A_PAD + t4];
            af[mi][1] = As[(r0 + g + 8) * A_PAD + t4];
            af[mi][2] = As[(r0 + g) * A_PAD + t4 + 4];
            af[mi][3] = As[(r0 + g + 8) * A_PAD + t4 + 4];
        }
#pragma unroll
        for (int mi = 0; mi < 2; mi++)
#pragma unroll
            for (int nt = 0; nt < 8; nt++)
                mma_tf32(acc[mi][nt], af[mi], bf[nt]);
        __syncthreads();
    }

    // epilogue
#pragma unroll
    for (int mi = 0; mi < 2; mi++) {
        const int rA = rowBase + warp_m * 32 + mi * 16 + g;
        const int rB = rA + 8;
        const float rsA = (rA < M) ? rowscale[rA] : 0.f;
        const float rsB = (rB < M) ? rowscale[rB] : 0.f;
#pragma unroll
        for (int nt = 0; nt < 8; nt++) {
            const int col = colBase + warp_n * 64 + nt * 8 + t4 * 2;
            const float bb0 = bias[col];
            const float bb1 = bias[col + 1];
            if (rA < M) {
                float v0 = fmaf(acc[mi][nt][0], rsA, bb0);
                float v1 = fmaf(acc[mi][nt][1], rsA, bb1);
                if (L == 0) { v0 = fmaxf(v0, 0.f); v1 = fmaxf(v1, 0.f); }
                C[(size_t)rA * N + col]     = v0;
                C[(size_t)rA * N + col + 1] = v1;
            }
            if (rB < M) {
                float v2 = fmaf(acc[mi][nt][2], rsB, bb0);
                float v3 = fmaf(acc[mi][nt][3], rsB, bb1);
                if (L == 0) { v2 = fmaxf(v2, 0.f); v3 = fmaxf(v3, 0.f); }
                C[(size_t)rB * N + col]     = v2;
                C[(size_t)rB * N + col + 1] = v3;
            }
        }
    }
}

// ---------------- launch ----------------
extern "C" void kernel_launch(void* const* d_in, const int* in_sizes, int n_in,
                              void* d_out, int out_size) {
    const float* features = (const float*)d_in[0];
    const float* W1       = (const float*)d_in[1];
    const float* b1       = (const float*)d_in[2];
    const float* W2       = (const float*)d_in[3];
    const float* b2       = (const float*)d_in[4];
    const int*   src0     = (const int*)d_in[5];
    const int*   dst0     = (const int*)d_in[6];
    const int*   src1     = (const int*)d_in[7];
    const int*   dst1     = (const int*)d_in[8];
    const int E0 = in_sizes[5];
    const int E1 = in_sizes[7];
    float* out = (float*)d_out;

    zero_kernel<<<512, 256>>>();
    deg_kernel<<<1024, 256>>>(src0, dst0, E0, src1, dst1, E1);
    norm_kernel<<<(N_SRC0 + 255) / 256, 256>>>();
    scanA_kernel<<<NBLK0 + NBLK1, 256>>>();
    scanB_kernel<<<1, 32>>>(E0, E1);
    scanC_kernel<<<NBLK0 + NBLK1, 256>>>();
    fill_kernel<<<1024, 256>>>(src0, dst0, E0, src1, dst1, E1);

    agg_gather_kernel<0><<<(N_DST0 + 3) / 4, 256>>>((const float4*)features);

    {
        dim3 grid(256 / 128, (N_DST0 + 127) / 128);
        mma_gemm_kernel<0><<<grid, 256>>>(W1, b1, nullptr);
    }

    agg_gather_kernel<1><<<(N_DST1 + 3) / 4, 256>>>(nullptr);

    {
        dim3 grid(128 / 128, (N_DST1 + 127) / 128);
        mma_gemm_kernel<1><<<grid, 256>>>(W2, b2, out);
    }
}